// round 1
// baseline (speedup 1.0000x reference)
#include <cuda_runtime.h>
#include <math.h>

// Problem shapes (fixed by the dataset)
#define SDIM 256
#define RDIM 8192
#define BDIM 8192

// GEMM tiling
#define BM 64
#define BK 16
#define TM 8
#define TN 8
#define THREADS 256

// 8 MB scratch: incidence transposed to [R][S] for coalesced loads
__device__ float g_incT[RDIM * SDIM];

// ---------------------------------------------------------------------------
// Kernel 1: transpose incidence [S][R] -> incT [R][S]
// ---------------------------------------------------------------------------
__global__ void transpose_kernel(const float* __restrict__ inc) {
    __shared__ float tile[32][33];
    int rBase = blockIdx.x * 32;
    int sBase = blockIdx.y * 32;
    int tx = threadIdx.x;   // 0..31
    int ty = threadIdx.y;   // 0..7
#pragma unroll
    for (int i = 0; i < 32; i += 8) {
        tile[ty + i][tx] = inc[(size_t)(sBase + ty + i) * RDIM + rBase + tx];
    }
    __syncthreads();
#pragma unroll
    for (int i = 0; i < 32; i += 8) {
        g_incT[(size_t)(rBase + ty + i) * SDIM + sBase + tx] = tile[tx][ty + i];
    }
}

// ---------------------------------------------------------------------------
// Kernel 2: fused flux + GEMM
//   out[b,s] = sum_r incT[r][s] * flux[b,r]
//   flux[b,r] = rate(b,r) * abPad[b, rm[r].x] * abPad[b, rm[r].y]
// Block: BM=64 batches x all 256 species. Loop K over R in BK=16 chunks.
// ---------------------------------------------------------------------------
__global__ __launch_bounds__(THREADS, 2)
void fused_flux_gemm(const float* __restrict__ ab,
                     const float* __restrict__ temperature,
                     const float* __restrict__ cr_rate,
                     const float* __restrict__ fuv_rate,
                     const float* __restrict__ alpha,
                     const float* __restrict__ beta,
                     const float* __restrict__ gam,
                     const int2*  __restrict__ rm,
                     const int*   __restrict__ rtype,
                     float* __restrict__ out)
{
    __shared__ float sFlux[BK][BM];
    __shared__ float sInc[BK][SDIM];
    __shared__ float sLt[BM], sInvT[BM], sCr[BM], sFuv[BM];

    const int t = threadIdx.x;
    const int bBase = blockIdx.x * BM;

    if (t < BM) {
        float T = temperature[bBase + t];
        sLt[t]   = logf(T * (1.0f / 300.0f));
        sInvT[t] = 1.0f / T;
        sCr[t]   = cr_rate[bBase + t];
        sFuv[t]  = fuv_rate[bBase + t];
    }
    __syncthreads();

    float acc[TM][TN];
#pragma unroll
    for (int i = 0; i < TM; i++)
#pragma unroll
        for (int j = 0; j < TN; j++) acc[i][j] = 0.0f;

    const int tx = t & 31;   // N-dim lane: covers columns tx + 32*j
    const int ty = t >> 5;   // M-dim warp row: covers rows ty*TM + i

    for (int k0 = 0; k0 < RDIM; k0 += BK) {
        // ---- Phase A: compute the 16x64 flux tile (4 elements per thread) ----
#pragma unroll
        for (int i = 0; i < 4; i++) {
            int idx = t + i * THREADS;       // 0..1023
            int kk = idx >> 6;               // 0..15
            int bb = idx & 63;               // 0..63
            int r = k0 + kk;
            int2 m = rm[r];
            const float* abRow = ab + (size_t)(bBase + bb) * SDIM;
            float a0 = (m.x < SDIM) ? abRow[m.x] : 1.0f;
            float a1 = (m.y < SDIM) ? abRow[m.y] : 1.0f;
            int rt = rtype[r];
            float al = alpha[r];
            float g = gam[r];
            float k;
            if (rt == 0) {
                k = al * __expf(fmaf(beta[r], sLt[bb], -g * sInvT[bb]));
            } else if (rt == 1) {
                k = al * sCr[bb];
            } else {
                k = al * __expf(-g) * sFuv[bb];
            }
            sFlux[kk][bb] = k * a0 * a1;
        }
        // ---- Phase B: load 16x256 incidence tile (float4, coalesced) ----
#pragma unroll
        for (int i = 0; i < 4; i++) {
            int idx = t + i * THREADS;       // 0..1023
            int kk = idx >> 6;               // 0..15
            int j  = idx & 63;               // float4 index 0..63
            float4 v = ((const float4*)(g_incT + (size_t)(k0 + kk) * SDIM))[j];
            ((float4*)sInc[kk])[j] = v;
        }
        __syncthreads();

        // ---- Phase C: 64x256x16 FFMA tile ----
#pragma unroll
        for (int kk = 0; kk < BK; kk++) {
            float a[TM], b[TN];
#pragma unroll
            for (int i = 0; i < TM; i++) a[i] = sFlux[kk][ty * TM + i];
#pragma unroll
            for (int j = 0; j < TN; j++) b[j] = sInc[kk][tx + 32 * j];
#pragma unroll
            for (int i = 0; i < TM; i++)
#pragma unroll
                for (int j = 0; j < TN; j++)
                    acc[i][j] = fmaf(a[i], b[j], acc[i][j]);
        }
        __syncthreads();
    }

    // ---- Epilogue: coalesced stores ----
#pragma unroll
    for (int i = 0; i < TM; i++) {
        float* orow = out + (size_t)(bBase + ty * TM + i) * SDIM;
#pragma unroll
        for (int j = 0; j < TN; j++) {
            orow[tx + 32 * j] = acc[i][j];
        }
    }
}

// ---------------------------------------------------------------------------
// Launch
// Inputs (metadata order):
//  0: time (B)            [unused]
//  1: abundances (B,S)
//  2: temperature (B)
//  3: cr_rate (B)
//  4: fuv_rate (B)
//  5: incidence (S,R)
//  6: alpha (R)
//  7: beta (R)
//  8: gamma (R)
//  9: reactant_multipliers (R,2) int32
// 10: rtype (R) int32
// ---------------------------------------------------------------------------
extern "C" void kernel_launch(void* const* d_in, const int* in_sizes, int n_in,
                              void* d_out, int out_size) {
    const float* ab   = (const float*)d_in[1];
    const float* temp = (const float*)d_in[2];
    const float* cr   = (const float*)d_in[3];
    const float* fuv  = (const float*)d_in[4];
    const float* inc  = (const float*)d_in[5];
    const float* alp  = (const float*)d_in[6];
    const float* bet  = (const float*)d_in[7];
    const float* gam  = (const float*)d_in[8];
    const int2*  rm   = (const int2*)d_in[9];
    const int*   rty  = (const int*)d_in[10];
    float* out = (float*)d_out;

    dim3 tgrid(RDIM / 32, SDIM / 32);
    dim3 tblk(32, 8);
    transpose_kernel<<<tgrid, tblk>>>(inc);

    fused_flux_gemm<<<BDIM / BM, THREADS>>>(ab, temp, cr, fuv, alp, bet, gam,
                                            rm, rty, out);
}

// round 3
// speedup vs baseline: 4.1285x; 4.1285x over previous
#include <cuda_runtime.h>
#include <math.h>
#include <stdint.h>

#define SDIM 256
#define RDIM 8192
#define BDIM 8192
#define BM 64
#define KC 32
#define NCHUNK (RDIM / KC)     // 256
#define THREADS 256

// ---- dynamic smem layout (bytes) ----
#define A_STAGE 8192                    // 64 x 32 tf32, fragment order
#define OFF_SA 0
#define OFF_SB (OFF_SA + 2 * A_STAGE)   // 16384
#define B_STAGE 32800                   // 4 ks * 2050 words (skewed), padded
#define OFF_AB (OFF_SB + 2 * B_STAGE)   // 81984
#define AB_STRIDE 257
#define SMEM_BYTES (OFF_AB + BM * AB_STRIDE * 4)   // 147776

__device__ __forceinline__ uint32_t smem_u32(const void* p) {
    uint32_t a;
    asm("{ .reg .u64 t; cvta.to.shared.u64 t, %1; cvt.u32.u64 %0, t; }" : "=r"(a) : "l"(p));
    return a;
}
__device__ __forceinline__ uint32_t to_tf32(float f) {
    uint32_t u;
    asm("cvt.rna.tf32.f32 %0, %1;" : "=r"(u) : "f"(f));
    return u;
}
__device__ __forceinline__ void sts128(uint32_t a, uint32_t x, uint32_t y, uint32_t z, uint32_t w) {
    asm volatile("st.shared.v4.b32 [%0], {%1,%2,%3,%4};" :: "r"(a), "r"(x), "r"(y), "r"(z), "r"(w) : "memory");
}
__device__ __forceinline__ void sts64(uint32_t a, uint32_t x, uint32_t y) {
    asm volatile("st.shared.v2.b32 [%0], {%1,%2};" :: "r"(a), "r"(x), "r"(y) : "memory");
}
__device__ __forceinline__ void lds128(uint32_t a, uint32_t* r) {
    asm volatile("ld.shared.v4.b32 {%0,%1,%2,%3}, [%4];"
                 : "=r"(r[0]), "=r"(r[1]), "=r"(r[2]), "=r"(r[3]) : "r"(a));
}
__device__ __forceinline__ void lds64(uint32_t a, uint32_t* r) {
    asm volatile("ld.shared.v2.b32 {%0,%1}, [%2];" : "=r"(r[0]), "=r"(r[1]) : "r"(a));
}
__device__ __forceinline__ void mma_tf32(float* c, const uint32_t* a, const uint32_t* b) {
    asm volatile("mma.sync.aligned.m16n8k8.row.col.f32.tf32.tf32.f32 "
                 "{%0,%1,%2,%3}, {%4,%5,%6,%7}, {%8,%9}, {%0,%1,%2,%3};"
                 : "+f"(c[0]), "+f"(c[1]), "+f"(c[2]), "+f"(c[3])
                 : "r"(a[0]), "r"(a[1]), "r"(a[2]), "r"(a[3]), "r"(b[0]), "r"(b[1]));
}

__global__ __launch_bounds__(THREADS, 1)
void fused_mma(const float* __restrict__ ab,
               const float* __restrict__ temperature,
               const float* __restrict__ cr_rate,
               const float* __restrict__ fuv_rate,
               const float* __restrict__ inc,
               const float* __restrict__ alpha,
               const float* __restrict__ beta,
               const float* __restrict__ gam,
               const int2*  __restrict__ rm,
               const int*   __restrict__ rtype,
               float* __restrict__ out)
{
    extern __shared__ char smem[];
    const uint32_t sb = smem_u32(smem);
    float* abT = (float*)(smem + OFF_AB);

    const int tid  = threadIdx.x;
    const int wid  = tid >> 5;
    const int lane = tid & 31;
    const int l4   = lane >> 2;      // 0..7
    const int kl   = lane & 3;       // 0..3
    const int bBase = blockIdx.x * BM;

    // ---- abundance tile [64][257-padded] ----
    {
        for (int i = 0; i < 16; i++) {
            int idx = tid + i * THREADS;        // 0..4095 (float4 units)
            int row = idx >> 6;                 // 0..63
            int q   = idx & 63;                 // 0..63
            float4 v = __ldg((const float4*)(ab + (size_t)(bBase + row) * SDIM) + q);
            float* dst = abT + row * AB_STRIDE + q * 4;
            dst[0] = v.x; dst[1] = v.y; dst[2] = v.z; dst[3] = v.w;
        }
    }

    // ---- per-thread producer constants ----
    const int wks = wid >> 1;               // producer ks (0..3)
    const int bm0 = (wid & 1) * 2;          // producer mtile base (0 or 2)
    const int b_base = bm0 * 16 + l4;       // + {0,8,16,24}
    float ltv[4], invTv[4], crv[4], fuvv[4];
#pragma unroll
    for (int j = 0; j < 4; j++) {
        int bg = bBase + b_base + 8 * j;
        float T = __ldg(temperature + bg);
        ltv[j]   = __logf(T * (1.0f / 300.0f));
        invTv[j] = 1.0f / T;
        crv[j]   = __ldg(cr_rate + bg);
        fuvv[j]  = __ldg(fuv_rate + bg);
    }

    // ---- consumer warp coords ----
    const int wm = wid >> 2;   // 0..1 (M)
    const int wn = wid & 3;    // 0..3 (N)

    float acc[2][8][4];
#pragma unroll
    for (int mt = 0; mt < 2; mt++)
#pragma unroll
        for (int nt = 0; nt < 8; nt++)
#pragma unroll
            for (int i = 0; i < 4; i++) acc[mt][nt][i] = 0.0f;

    auto produce = [&](int c, int st) {
        const int cb = c * KC;
        // ---- B tile: inc -> skewed fragment layout ----
        const uint32_t bB = sb + OFF_SB + st * B_STAGE;
#pragma unroll
        for (int it = 0; it < 4; it++) {
            int s  = it * 64 + (tid >> 2);
            int ks = tid & 3;
            const float* src = inc + (size_t)s * RDIM + cb + ks * 8;
            float4 v0 = __ldg((const float4*)src);
            float4 v1 = __ldg((const float4*)src + 1);
            uint32_t t0 = to_tf32(v0.x), t1 = to_tf32(v0.y), t2 = to_tf32(v0.z), t3 = to_tf32(v0.w);
            uint32_t t4 = to_tf32(v1.x), t5 = to_tf32(v1.y), t6 = to_tf32(v1.z), t7 = to_tf32(v1.w);
            uint32_t base = bB + (uint32_t)(ks * 2050 + s * 8) * 4;
            sts64(base +  0, t0, t4);
            sts64(base +  8, t1, t5);
            sts64(base + 16, t2, t6);
            sts64(base + 24, t3, t7);
        }
        // ---- A tile: flux in fragment order ----
        const int r0 = cb + wks * 8 + kl;
        const int r1 = r0 + 4;
        int2 m0 = __ldg(rm + r0);
        int2 m1 = __ldg(rm + r1);
        float al0 = __ldg(alpha + r0), al1 = __ldg(alpha + r1);
        float be0 = __ldg(beta  + r0), be1 = __ldg(beta  + r1);
        float ga0 = __ldg(gam   + r0), ga1 = __ldg(gam   + r1);
        int   rt0 = __ldg(rtype + r0), rt1 = __ldg(rtype + r1);

        float f[2][4];
#pragma unroll
        for (int j = 0; j < 4; j++) {
            const float* abRow = abT + (b_base + 8 * j) * AB_STRIDE;
            // r0
            {
                float a0 = (m0.x < SDIM) ? abRow[m0.x] : 1.0f;
                float a1 = (m0.y < SDIM) ? abRow[m0.y] : 1.0f;
                float x  = (rt0 == 0) ? fmaf(be0, ltv[j], -ga0 * invTv[j])
                                      : ((rt0 == 1) ? 0.0f : -ga0);
                float mm = (rt0 == 0) ? 1.0f : ((rt0 == 1) ? crv[j] : fuvv[j]);
                f[0][j] = al0 * __expf(x) * mm * a0 * a1;
            }
            // r1
            {
                float a0 = (m1.x < SDIM) ? abRow[m1.x] : 1.0f;
                float a1 = (m1.y < SDIM) ? abRow[m1.y] : 1.0f;
                float x  = (rt1 == 0) ? fmaf(be1, ltv[j], -ga1 * invTv[j])
                                      : ((rt1 == 1) ? 0.0f : -ga1);
                float mm = (rt1 == 0) ? 1.0f : ((rt1 == 1) ? crv[j] : fuvv[j]);
                f[1][j] = al1 * __expf(x) * mm * a0 * a1;
            }
        }
        const uint32_t aB = sb + OFF_SA + st * A_STAGE;
        sts128(aB + (uint32_t)(((wks * 4 + bm0) * 32 + lane) * 16),
               to_tf32(f[0][0]), to_tf32(f[0][1]), to_tf32(f[1][0]), to_tf32(f[1][1]));
        sts128(aB + (uint32_t)(((wks * 4 + bm0 + 1) * 32 + lane) * 16),
               to_tf32(f[0][2]), to_tf32(f[0][3]), to_tf32(f[1][2]), to_tf32(f[1][3]));
    };

    auto consume = [&](int st) {
        const uint32_t aB = sb + OFF_SA + st * A_STAGE;
        const uint32_t bB = sb + OFF_SB + st * B_STAGE;
#pragma unroll
        for (int ks = 0; ks < 4; ks++) {
            uint32_t afr[2][4];
#pragma unroll
            for (int mt = 0; mt < 2; mt++)
                lds128(aB + (uint32_t)(((ks * 4 + wm * 2 + mt) * 32 + lane) * 16), afr[mt]);
            uint32_t bfr[8][2];
#pragma unroll
            for (int nt = 0; nt < 8; nt++) {
                int s = wn * 64 + nt * 8 + l4;
                lds64(bB + (uint32_t)((ks * 2050 + s * 8 + kl * 2) * 4), bfr[nt]);
            }
#pragma unroll
            for (int mt = 0; mt < 2; mt++)
#pragma unroll
                for (int nt = 0; nt < 8; nt++)
                    mma_tf32(acc[mt][nt], afr[mt], bfr[nt]);
        }
    };

    __syncthreads();   // abT ready
    produce(0, 0);
    __syncthreads();

#pragma unroll 1
    for (int c = 0; c < NCHUNK; c++) {
        int st = c & 1;
        if (c + 1 < NCHUNK) produce(c + 1, st ^ 1);
        consume(st);
        __syncthreads();
    }

    // ---- epilogue ----
#pragma unroll
    for (int mt = 0; mt < 2; mt++) {
#pragma unroll
        for (int nt = 0; nt < 8; nt++) {
            int row0 = bBase + wm * 32 + mt * 16 + l4;
            int col  = wn * 64 + nt * 8 + 2 * kl;
            float2 v0 = make_float2(acc[mt][nt][0], acc[mt][nt][1]);
            float2 v1 = make_float2(acc[mt][nt][2], acc[mt][nt][3]);
            *(float2*)(out + (size_t)row0 * SDIM + col) = v0;
            *(float2*)(out + (size_t)(row0 + 8) * SDIM + col) = v1;
        }
    }
}

extern "C" void kernel_launch(void* const* d_in, const int* in_sizes, int n_in,
                              void* d_out, int out_size) {
    const float* ab   = (const float*)d_in[1];
    const float* temp = (const float*)d_in[2];
    const float* cr   = (const float*)d_in[3];
    const float* fuv  = (const float*)d_in[4];
    const float* inc  = (const float*)d_in[5];
    const float* alp  = (const float*)d_in[6];
    const float* bet  = (const float*)d_in[7];
    const float* gam  = (const float*)d_in[8];
    const int2*  rm   = (const int2*)d_in[9];
    const int*   rty  = (const int*)d_in[10];
    float* out = (float*)d_out;

    cudaFuncSetAttribute(fused_mma, cudaFuncAttributeMaxDynamicSharedMemorySize, SMEM_BYTES);
    fused_mma<<<BDIM / BM, THREADS, SMEM_BYTES>>>(ab, temp, cr, fuv, inc, alp, bet, gam,
                                                  rm, rty, out);
}